// round 1
// baseline (speedup 1.0000x reference)
#include <cuda_runtime.h>
#include <cuda_bf16.h>

// ---------------- problem constants ----------------
#define N_CB 4
#define M_CODES 512
#define D_DIM 32
#define L_LAT 64
#define B_BATCH 1024
#define T_POS (B_BATCH * L_LAT)          // 65536 per codebook

// output layout (float32, reference tuple order, flattened+concatenated)
#define OFF_ZQ   0ULL
#define OFF_LOSS 8388608ULL
#define OFF_PERP 8388609ULL
#define OFF_IDX  8388610ULL
#define OFF_EMB  8650754ULL
#define OFF_CNT  8716290ULL
#define OFF_W    8718338ULL

#define SMEM_BYTES (M_CODES * D_DIM * 8 + M_CODES * 8)   // dup-e (131072) + dup-esq (4096)

// ---------------- scratch (device globals; no allocations allowed) ----------------
__device__ int    g_counts[N_CB * M_CODES];
__device__ float  g_dw[N_CB * M_CODES * D_DIM];
__device__ double g_loss;

// ---------------- packed f32x2 helpers ----------------
__device__ __forceinline__ unsigned long long pk2(float lo, float hi) {
    unsigned long long r;
    asm("mov.b64 %0, {%1, %2};" : "=l"(r) : "f"(lo), "f"(hi));
    return r;
}
__device__ __forceinline__ void upk2(unsigned long long v, float& lo, float& hi) {
    asm("mov.b64 {%0, %1}, %2;" : "=f"(lo), "=f"(hi) : "l"(v));
}
__device__ __forceinline__ unsigned long long fma2(unsigned long long a, unsigned long long b,
                                                   unsigned long long c) {
    unsigned long long d;
    asm("fma.rn.f32x2 %0, %1, %2, %3;" : "=l"(d) : "l"(a), "l"(b), "l"(c));
    return d;
}
__device__ __forceinline__ unsigned long long add2(unsigned long long a, unsigned long long b) {
    unsigned long long d;
    asm("add.rn.f32x2 %0, %1, %2;" : "=l"(d) : "l"(a), "l"(b));
    return d;
}

// ---------------- kernel 0: zero scratch ----------------
__global__ void vq_zero(float* __restrict__ out) {
    int i = blockIdx.x * blockDim.x + threadIdx.x;
    if (i < N_CB * M_CODES * D_DIM) g_dw[i] = 0.0f;
    if (i < N_CB * M_CODES)         g_counts[i] = 0;
    if (i == 0) { g_loss = 0.0; out[OFF_PERP] = 0.0f; }
}

// ---------------- kernel 1: distances + argmin + z_q + scatter + loss ----------------
// grid: (T/512, N_CB), block: 256. Each thread handles 2 positions packed into f32x2 lanes.
__global__ void __launch_bounds__(256) vq_main(const float* __restrict__ x,
                                               const float* __restrict__ emb,
                                               float* __restrict__ out) {
    const int n    = blockIdx.y;
    const int tile = blockIdx.x;
    const int tid  = threadIdx.x;

    extern __shared__ float2 sm[];
    float2* sE2   = sm;                        // [M_CODES*D_DIM] each = (e, e)
    float2* sEsq2 = sm + M_CODES * D_DIM;      // [M_CODES]       each = (e_sq, e_sq)

    // load embedding[n] duplicated
    const float* en = emb + (size_t)n * M_CODES * D_DIM;
    for (int i = tid; i < M_CODES * D_DIM; i += 256) {
        float v = en[i];
        sE2[i] = make_float2(v, v);
    }
    __syncthreads();
    for (int m = tid; m < M_CODES; m += 256) {
        float s = 0.0f;
#pragma unroll
        for (int d = 0; d < D_DIM; d++) {
            float v = sE2[m * D_DIM + d].x;
            s = fmaf(v, v, s);
        }
        sEsq2[m] = make_float2(s, s);
    }

    // load the two x vectors for this thread (positions t0, t0+256)
    const int t0 = tile * 512 + tid;
    const int t1 = t0 + 256;
    const int b0 = t0 >> 6, l0 = t0 & 63;
    const int b1 = t1 >> 6, l1 = t1 & 63;
    const float* px0 = x + (size_t)b0 * 8192 + (size_t)n * 2048 + l0;
    const float* px1 = x + (size_t)b1 * 8192 + (size_t)n * 2048 + l1;

    unsigned long long xp[D_DIM];
    float xs0 = 0.0f, xs1 = 0.0f;
#pragma unroll
    for (int d = 0; d < D_DIM; d++) {
        float a = px0[d * 64];
        float b = px1[d * 64];
        xp[d] = pk2(a, b);
        xs0 = fmaf(a, a, xs0);
        xs1 = fmaf(b, b, xs1);
    }
    const unsigned long long xsp  = pk2(xs0, xs1);
    const unsigned long long NEG2 = pk2(-2.0f, -2.0f);
    __syncthreads();

    // ---- main search: dist = (e_sq + x_sq) - 2*dot, fp32, first-index-wins ----
    float best0 = 3.402823466e38f, best1 = 3.402823466e38f;
    int   i0 = 0, i1 = 0;
    for (int m = 0; m < M_CODES; m++) {
        const ulonglong2* er = (const ulonglong2*)(sE2 + m * D_DIM);
        unsigned long long a0 = 0ULL, a1 = 0ULL, a2 = 0ULL, a3 = 0ULL;
#pragma unroll
        for (int k = 0; k < 8; k++) {
            ulonglong2 e0 = er[2 * k];
            ulonglong2 e1 = er[2 * k + 1];
            a0 = fma2(xp[4 * k + 0], e0.x, a0);
            a1 = fma2(xp[4 * k + 1], e0.y, a1);
            a2 = fma2(xp[4 * k + 2], e1.x, a2);
            a3 = fma2(xp[4 * k + 3], e1.y, a3);
        }
        unsigned long long dot = add2(add2(a0, a1), add2(a2, a3));
        unsigned long long A   = add2(xsp, *(const unsigned long long*)&sEsq2[m]);
        unsigned long long dd  = fma2(dot, NEG2, A);
        float d0, d1;
        upk2(dd, d0, d1);
        if (d0 < best0) { best0 = d0; i0 = m; }
        if (d1 < best1) { best1 = d1; i1 = m; }
    }

    // ---- outputs: indices, z_q ((q+x)-x), dw scatter, counts, loss ----
    float lloss = 0.0f;

    out[OFF_IDX + (size_t)b0 * 256 + (size_t)n * 64 + l0] = (float)i0;
    atomicAdd(&g_counts[n * M_CODES + i0], 1);
    {
        float* dwp = g_dw + ((size_t)n * M_CODES + i0) * D_DIM;
        float* zq  = out + OFF_ZQ + (size_t)b0 * 8192 + (size_t)n * 2048 + l0;
#pragma unroll
        for (int d = 0; d < D_DIM; d++) {
            float xv, hv;
            upk2(xp[d], xv, hv);
            float q = sE2[i0 * D_DIM + d].x;
            zq[d * 64] = __fsub_rn(__fadd_rn(q, xv), xv);
            float df = xv - q;
            lloss = fmaf(df, df, lloss);
            atomicAdd(dwp + d, xv);
        }
    }

    out[OFF_IDX + (size_t)b1 * 256 + (size_t)n * 64 + l1] = (float)i1;
    atomicAdd(&g_counts[n * M_CODES + i1], 1);
    {
        float* dwp = g_dw + ((size_t)n * M_CODES + i1) * D_DIM;
        float* zq  = out + OFF_ZQ + (size_t)b1 * 8192 + (size_t)n * 2048 + l1;
#pragma unroll
        for (int d = 0; d < D_DIM; d++) {
            float xv, hv;
            upk2(xp[d], xv, hv);
            float q = sE2[i1 * D_DIM + d].x;
            zq[d * 64] = __fsub_rn(__fadd_rn(q, hv), hv);
            float df = hv - q;
            lloss = fmaf(df, df, lloss);
            atomicAdd(dwp + d, hv);
        }
    }

    // CTA loss reduction -> one double atomic per CTA
#pragma unroll
    for (int o = 16; o > 0; o >>= 1) lloss += __shfl_down_sync(0xFFFFFFFFu, lloss, o);
    __shared__ float wsum[8];
    const int warp = tid >> 5, lane = tid & 31;
    if (lane == 0) wsum[warp] = lloss;
    __syncthreads();
    if (tid == 0) {
        double s = 0.0;
#pragma unroll
        for (int w = 0; w < 8; w++) s += (double)wsum[w];
        atomicAdd(&g_loss, s);
    }
}

// ---------------- kernel 2: EMA / Laplace / embedding / perplexity / loss ----------------
__global__ void vq_fin(const float* __restrict__ ema_c,
                       const float* __restrict__ ema_w,
                       float* __restrict__ out) {
    const int n = blockIdx.x;
    const int m = threadIdx.x;   // 512 threads
    __shared__ float red[M_CODES];

    const float DECAY = 0.999f;
    const float OMD   = (float)(1.0 - 0.999);         // matches python 1.0-DECAY cast to f32
    const float MEPS  = (float)(512.0 * 1e-5);

    float cnt  = (float)g_counts[n * M_CODES + m];
    float cnew = DECAY * ema_c[n * M_CODES + m] + OMD * cnt;

    red[m] = cnew;
    __syncthreads();
    for (int s = 256; s > 0; s >>= 1) {
        if (m < s) red[m] += red[m + s];
        __syncthreads();
    }
    float ntot = red[0];
    __syncthreads();

    float clap = (cnew + 1e-5f) / (ntot + MEPS) * ntot;
    out[OFF_CNT + (size_t)n * M_CODES + m] = clap;

#pragma unroll
    for (int d = 0; d < D_DIM; d++) {
        size_t idx = ((size_t)n * M_CODES + m) * D_DIM + d;
        float w = DECAY * ema_w[idx] + OMD * g_dw[idx];
        out[OFF_W + idx]   = w;
        out[OFF_EMB + idx] = w / clap;
    }

    // perplexity per codebook
    float p    = cnt * (1.0f / 65536.0f);
    float term = p * logf(p + 1e-10f);
    red[m] = term;
    __syncthreads();
    for (int s = 256; s > 0; s >>= 1) {
        if (m < s) red[m] += red[m + s];
        __syncthreads();
    }
    if (m == 0) {
        atomicAdd(&out[OFF_PERP], expf(-red[0]));
        if (n == 0) out[OFF_LOSS] = (float)(0.25 * g_loss * (1.0 / 8388608.0));
    }
}

// ---------------- launch ----------------
extern "C" void kernel_launch(void* const* d_in, const int* in_sizes, int n_in,
                              void* d_out, int out_size) {
    const float* x     = (const float*)d_in[0];
    const float* emb   = (const float*)d_in[1];
    const float* ema_c = (const float*)d_in[2];
    const float* ema_w = (const float*)d_in[3];
    float* out = (float*)d_out;

    cudaFuncSetAttribute(vq_main, cudaFuncAttributeMaxDynamicSharedMemorySize, SMEM_BYTES);

    vq_zero<<<256, 256>>>(out);
    vq_main<<<dim3(T_POS / 512, N_CB), 256, SMEM_BYTES>>>(x, emb, out);
    vq_fin<<<N_CB, M_CODES>>>(ema_c, ema_w, out);
}

// round 2
// speedup vs baseline: 1.1768x; 1.1768x over previous
#include <cuda_runtime.h>
#include <cuda_bf16.h>

// ---------------- problem constants ----------------
#define N_CB 4
#define M_CODES 512
#define D_DIM 32
#define L_LAT 64
#define B_BATCH 1024
#define T_POS (B_BATCH * L_LAT)          // 65536 per codebook

// output layout (float32, reference tuple order, flattened+concatenated)
#define OFF_ZQ   0ULL
#define OFF_LOSS 8388608ULL
#define OFF_PERP 8388609ULL
#define OFF_IDX  8388610ULL
#define OFF_EMB  8650754ULL
#define OFF_CNT  8716290ULL
#define OFF_W    8718338ULL

#define SMEM_BYTES (M_CODES * D_DIM * 8 + M_CODES * 8)   // dup-e (131072) + dup-esq (4096)

// ---------------- scratch (device globals; no allocations allowed) ----------------
__device__ int    g_counts[N_CB * M_CODES];
__device__ float  g_dw[N_CB * M_CODES * D_DIM];
__device__ double g_loss;

// ---------------- packed f32x2 helpers ----------------
__device__ __forceinline__ unsigned long long pk2(float lo, float hi) {
    unsigned long long r;
    asm("mov.b64 %0, {%1, %2};" : "=l"(r) : "f"(lo), "f"(hi));
    return r;
}
__device__ __forceinline__ void upk2(unsigned long long v, float& lo, float& hi) {
    asm("mov.b64 {%0, %1}, %2;" : "=f"(lo), "=f"(hi) : "l"(v));
}
__device__ __forceinline__ unsigned long long fma2(unsigned long long a, unsigned long long b,
                                                   unsigned long long c) {
    unsigned long long d;
    asm("fma.rn.f32x2 %0, %1, %2, %3;" : "=l"(d) : "l"(a), "l"(b), "l"(c));
    return d;
}
__device__ __forceinline__ unsigned long long add2(unsigned long long a, unsigned long long b) {
    unsigned long long d;
    asm("add.rn.f32x2 %0, %1, %2;" : "=l"(d) : "l"(a), "l"(b));
    return d;
}

// ---------------- kernel 0: zero scratch ----------------
__global__ void vq_zero(float* __restrict__ out) {
    int i = blockIdx.x * blockDim.x + threadIdx.x;
    if (i < N_CB * M_CODES * D_DIM) g_dw[i] = 0.0f;
    if (i < N_CB * M_CODES)         g_counts[i] = 0;
    if (i == 0) { g_loss = 0.0; out[OFF_PERP] = 0.0f; }
}

// ---------------- kernel 1: distances + argmin + z_q + scatter + loss ----------------
// grid: (T/1024, N_CB), block: 256. Each thread handles 4 positions as two f32x2 pairs.
__global__ void __launch_bounds__(256) vq_main(const float* __restrict__ x,
                                               const float* __restrict__ emb,
                                               float* __restrict__ out) {
    const int n    = blockIdx.y;
    const int tile = blockIdx.x;
    const int tid  = threadIdx.x;

    extern __shared__ float2 sm[];
    float2* sE2   = sm;                        // [M_CODES*D_DIM] each = (e, e)
    float2* sEsq2 = sm + M_CODES * D_DIM;      // [M_CODES]       each = (e_sq, e_sq)

    // load embedding[n] duplicated
    const float* en = emb + (size_t)n * M_CODES * D_DIM;
    for (int i = tid; i < M_CODES * D_DIM; i += 256) {
        float v = en[i];
        sE2[i] = make_float2(v, v);
    }
    __syncthreads();
    for (int m = tid; m < M_CODES; m += 256) {
        float s = 0.0f;
#pragma unroll
        for (int d = 0; d < D_DIM; d++) {
            float v = sE2[m * D_DIM + d].x;
            s = fmaf(v, v, s);
        }
        sEsq2[m] = make_float2(s, s);
    }

    // four positions for this thread: t0, t0+256, t0+512, t0+768
    const int t0 = tile * 1024 + tid;
    int tpos[4];
    tpos[0] = t0; tpos[1] = t0 + 256; tpos[2] = t0 + 512; tpos[3] = t0 + 768;

    unsigned long long xpA[D_DIM];   // lanes = (t0, t1)
    unsigned long long xpB[D_DIM];   // lanes = (t2, t3)
    float xs[4] = {0.f, 0.f, 0.f, 0.f};
    {
        const float* p0 = x + (size_t)(tpos[0] >> 6) * 8192 + (size_t)n * 2048 + (tpos[0] & 63);
        const float* p1 = x + (size_t)(tpos[1] >> 6) * 8192 + (size_t)n * 2048 + (tpos[1] & 63);
        const float* p2 = x + (size_t)(tpos[2] >> 6) * 8192 + (size_t)n * 2048 + (tpos[2] & 63);
        const float* p3 = x + (size_t)(tpos[3] >> 6) * 8192 + (size_t)n * 2048 + (tpos[3] & 63);
#pragma unroll
        for (int d = 0; d < D_DIM; d++) {
            float a = p0[d * 64], b = p1[d * 64], c = p2[d * 64], e = p3[d * 64];
            xpA[d] = pk2(a, b);
            xpB[d] = pk2(c, e);
            xs[0] = fmaf(a, a, xs[0]);
            xs[1] = fmaf(b, b, xs[1]);
            xs[2] = fmaf(c, c, xs[2]);
            xs[3] = fmaf(e, e, xs[3]);
        }
    }
    const unsigned long long xsA  = pk2(xs[0], xs[1]);
    const unsigned long long xsB  = pk2(xs[2], xs[3]);
    const unsigned long long NEG2 = pk2(-2.0f, -2.0f);
    __syncthreads();

    // ---- main search: dist = (e_sq + x_sq) - 2*dot, fp32, first-index-wins ----
    float best[4] = {3.402823466e38f, 3.402823466e38f, 3.402823466e38f, 3.402823466e38f};
    int   bidx[4] = {0, 0, 0, 0};

    for (int m = 0; m < M_CODES; m++) {
        const ulonglong2* er = (const ulonglong2*)(sE2 + m * D_DIM);
        unsigned long long a0 = 0ULL, a1 = 0ULL, a2 = 0ULL, a3 = 0ULL;
        unsigned long long b0 = 0ULL, b1 = 0ULL, b2 = 0ULL, b3 = 0ULL;
#pragma unroll
        for (int k = 0; k < 8; k++) {
            ulonglong2 e0 = er[2 * k];
            ulonglong2 e1 = er[2 * k + 1];
            a0 = fma2(xpA[4 * k + 0], e0.x, a0);
            b0 = fma2(xpB[4 * k + 0], e0.x, b0);
            a1 = fma2(xpA[4 * k + 1], e0.y, a1);
            b1 = fma2(xpB[4 * k + 1], e0.y, b1);
            a2 = fma2(xpA[4 * k + 2], e1.x, a2);
            b2 = fma2(xpB[4 * k + 2], e1.x, b2);
            a3 = fma2(xpA[4 * k + 3], e1.y, a3);
            b3 = fma2(xpB[4 * k + 3], e1.y, b3);
        }
        unsigned long long esq  = *(const unsigned long long*)&sEsq2[m];
        unsigned long long dotA = add2(add2(a0, a1), add2(a2, a3));
        unsigned long long dotB = add2(add2(b0, b1), add2(b2, b3));
        unsigned long long ddA  = fma2(dotA, NEG2, add2(xsA, esq));
        unsigned long long ddB  = fma2(dotB, NEG2, add2(xsB, esq));
        float d0, d1, d2, d3;
        upk2(ddA, d0, d1);
        upk2(ddB, d2, d3);
        if (d0 < best[0]) { best[0] = d0; bidx[0] = m; }
        if (d1 < best[1]) { best[1] = d1; bidx[1] = m; }
        if (d2 < best[2]) { best[2] = d2; bidx[2] = m; }
        if (d3 < best[3]) { best[3] = d3; bidx[3] = m; }
    }

    // ---- outputs: indices, z_q ((q+x)-x), dw scatter, counts, loss ----
    float lloss = 0.0f;

#pragma unroll
    for (int p = 0; p < 4; p++) {
        const int t = tpos[p];
        const int b = t >> 6, l = t & 63;
        const int mi = bidx[p];
        out[OFF_IDX + (size_t)b * 256 + (size_t)n * 64 + l] = (float)mi;
        atomicAdd(&g_counts[n * M_CODES + mi], 1);
        float* dwp = g_dw + ((size_t)n * M_CODES + mi) * D_DIM;
        float* zq  = out + OFF_ZQ + (size_t)b * 8192 + (size_t)n * 2048 + l;
#pragma unroll
        for (int d = 0; d < D_DIM; d++) {
            float lo, hi;
            if (p < 2) upk2(xpA[d], lo, hi); else upk2(xpB[d], lo, hi);
            float xv = (p & 1) ? hi : lo;
            float q  = sE2[mi * D_DIM + d].x;
            zq[d * 64] = __fsub_rn(__fadd_rn(q, xv), xv);
            float df = xv - q;
            lloss = fmaf(df, df, lloss);
            atomicAdd(dwp + d, xv);
        }
    }

    // CTA loss reduction -> one double atomic per CTA
#pragma unroll
    for (int o = 16; o > 0; o >>= 1) lloss += __shfl_down_sync(0xFFFFFFFFu, lloss, o);
    __shared__ float wsum[8];
    const int warp = tid >> 5, lane = tid & 31;
    if (lane == 0) wsum[warp] = lloss;
    __syncthreads();
    if (tid == 0) {
        double s = 0.0;
#pragma unroll
        for (int w = 0; w < 8; w++) s += (double)wsum[w];
        atomicAdd(&g_loss, s);
    }
}

// ---------------- kernel 2: EMA / Laplace / embedding / perplexity / loss ----------------
__global__ void vq_fin(const float* __restrict__ ema_c,
                       const float* __restrict__ ema_w,
                       float* __restrict__ out) {
    const int n = blockIdx.x;
    const int m = threadIdx.x;   // 512 threads
    __shared__ float red[M_CODES];

    const float DECAY = 0.999f;
    const float OMD   = (float)(1.0 - 0.999);
    const float MEPS  = (float)(512.0 * 1e-5);

    float cnt  = (float)g_counts[n * M_CODES + m];
    float cnew = DECAY * ema_c[n * M_CODES + m] + OMD * cnt;

    red[m] = cnew;
    __syncthreads();
    for (int s = 256; s > 0; s >>= 1) {
        if (m < s) red[m] += red[m + s];
        __syncthreads();
    }
    float ntot = red[0];
    __syncthreads();

    float clap = (cnew + 1e-5f) / (ntot + MEPS) * ntot;
    out[OFF_CNT + (size_t)n * M_CODES + m] = clap;

#pragma unroll
    for (int d = 0; d < D_DIM; d++) {
        size_t idx = ((size_t)n * M_CODES + m) * D_DIM + d;
        float w = DECAY * ema_w[idx] + OMD * g_dw[idx];
        out[OFF_W + idx]   = w;
        out[OFF_EMB + idx] = w / clap;
    }

    // perplexity per codebook
    float p    = cnt * (1.0f / 65536.0f);
    float term = p * logf(p + 1e-10f);
    red[m] = term;
    __syncthreads();
    for (int s = 256; s > 0; s >>= 1) {
        if (m < s) red[m] += red[m + s];
        __syncthreads();
    }
    if (m == 0) {
        atomicAdd(&out[OFF_PERP], expf(-red[0]));
        if (n == 0) out[OFF_LOSS] = (float)(0.25 * g_loss * (1.0 / 8388608.0));
    }
}

// ---------------- launch ----------------
extern "C" void kernel_launch(void* const* d_in, const int* in_sizes, int n_in,
                              void* d_out, int out_size) {
    const float* x     = (const float*)d_in[0];
    const float* emb   = (const float*)d_in[1];
    const float* ema_c = (const float*)d_in[2];
    const float* ema_w = (const float*)d_in[3];
    float* out = (float*)d_out;

    cudaFuncSetAttribute(vq_main, cudaFuncAttributeMaxDynamicSharedMemorySize, SMEM_BYTES);

    vq_zero<<<256, 256>>>(out);
    vq_main<<<dim3(T_POS / 1024, N_CB), 256, SMEM_BYTES>>>(x, emb, out);
    vq_fin<<<N_CB, M_CODES>>>(ema_c, ema_w, out);
}

// round 3
// speedup vs baseline: 1.2367x; 1.0510x over previous
#include <cuda_runtime.h>
#include <cuda_bf16.h>

// ---------------- problem constants ----------------
#define N_CB 4
#define M_CODES 512
#define D_DIM 32
#define T_POS 65536

// output layout (float32, reference tuple order, flattened+concatenated)
#define OFF_ZQ   0ULL
#define OFF_LOSS 8388608ULL
#define OFF_PERP 8388609ULL
#define OFF_IDX  8388610ULL
#define OFF_EMB  8650754ULL
#define OFF_CNT  8716290ULL
#define OFF_W    8718338ULL

// ---------------- smem layout (bytes) ----------------
// sE   : [32][514] float2  (dup e, transposed, padded)   131584
// sX   : [32][128] float2  (position pairs)               32768
// sEsq : [512] float2 (dup)                                4096
// sXsq : [128] float2 (per-pair x_sq, lanes = 2 positions) 1024
// sBest: [256][8] float                                    8192
// sIdx : [256][8] int                                      8192
#define SE_OFF    0
#define SX_OFF    131584
#define SESQ_OFF  164352
#define SXSQ_OFF  168448
#define SBEST_OFF 169472
#define SIDX_OFF  177664
#define SMEM_BYTES 185856
#define SE_STRIDE 514   // float2 per d-row

// ---------------- scratch ----------------
__device__ int    g_counts[N_CB * M_CODES];
__device__ float  g_dw[N_CB * M_CODES * D_DIM];
__device__ double g_loss;

// ---------------- packed f32x2 helpers ----------------
__device__ __forceinline__ unsigned long long pk2(float lo, float hi) {
    unsigned long long r;
    asm("mov.b64 %0, {%1, %2};" : "=l"(r) : "f"(lo), "f"(hi));
    return r;
}
__device__ __forceinline__ void upk2(unsigned long long v, float& lo, float& hi) {
    asm("mov.b64 {%0, %1}, %2;" : "=f"(lo), "=f"(hi) : "l"(v));
}
__device__ __forceinline__ unsigned long long fma2(unsigned long long a, unsigned long long b,
                                                   unsigned long long c) {
    unsigned long long d;
    asm("fma.rn.f32x2 %0, %1, %2, %3;" : "=l"(d) : "l"(a), "l"(b), "l"(c));
    return d;
}
__device__ __forceinline__ unsigned long long add2(unsigned long long a, unsigned long long b) {
    unsigned long long d;
    asm("add.rn.f32x2 %0, %1, %2;" : "=l"(d) : "l"(a), "l"(b));
    return d;
}

// ---------------- kernel 0: zero scratch ----------------
__global__ void vq_zero(float* __restrict__ out) {
    int i = blockIdx.x * blockDim.x + threadIdx.x;
    if (i < N_CB * M_CODES * D_DIM) g_dw[i] = 0.0f;
    if (i < N_CB * M_CODES)         g_counts[i] = 0;
    if (i == 0) { g_loss = 0.0; out[OFF_PERP] = 0.0f; }
}

// ---------------- kernel 1: GEMM-tiled distances + argmin + epilogue ----------------
// grid (256 tiles, N_CB), block 256.
// CTA tile: 256 positions x 512 codes. Thread: 8 positions (4 f32x2 pairs) x 8 codes
// per block-iter; each warp owns a disjoint 64-code slice (warp w -> codes [64w, 64w+64)).
__global__ void __launch_bounds__(256) vq_main(const float* __restrict__ x,
                                               const float* __restrict__ emb,
                                               float* __restrict__ out) {
    const int n    = blockIdx.y;
    const int tile = blockIdx.x;
    const int tid  = threadIdx.x;

    extern __shared__ unsigned char smraw[];
    float2* sE   = (float2*)(smraw + SE_OFF);
    float2* sX   = (float2*)(smraw + SX_OFF);
    float2* sEsq = (float2*)(smraw + SESQ_OFF);
    float2* sXsq = (float2*)(smraw + SXSQ_OFF);
    float*  sBest = (float*)(smraw + SBEST_OFF);
    int*    sIdx  = (int*)(smraw + SIDX_OFF);
    __shared__ float wsum[8];

    // ---- fill e (dup + transpose), coalesced gmem reads ----
    const float* en = emb + (size_t)n * M_CODES * D_DIM;
    for (int idx = tid; idx < M_CODES * D_DIM; idx += 256) {
        int d = idx & 31, m = idx >> 5;
        float v = en[idx];
        sE[d * SE_STRIDE + m] = make_float2(v, v);
    }

    // ---- fill x pairs: pair p = positions (2p, 2p+1) of this tile ----
    for (int idx = tid; idx < 32 * 128; idx += 256) {
        int d = idx >> 7, p = idx & 127;
        int tl = 2 * p;
        int b  = tile * 4 + (tl >> 6);
        int l  = tl & 63;
        sX[d * 128 + p] = *(const float2*)(x + (size_t)b * 8192 + (size_t)n * 2048 + d * 64 + l);
    }
    __syncthreads();

    // ---- e_sq (dup), fmaf chain ascending d ----
    for (int m = tid; m < M_CODES; m += 256) {
        float s = 0.0f;
#pragma unroll
        for (int d = 0; d < D_DIM; d++) {
            float v = sE[d * SE_STRIDE + m].x;
            s = fmaf(v, v, s);
        }
        sEsq[m] = make_float2(s, s);
    }
    // ---- x_sq per pair ----
    if (tid < 128) {
        float s0 = 0.0f, s1 = 0.0f;
#pragma unroll
        for (int d = 0; d < D_DIM; d++) {
            float2 v = sX[d * 128 + tid];
            s0 = fmaf(v.x, v.x, s0);
            s1 = fmaf(v.y, v.y, s1);
        }
        sXsq[tid] = make_float2(s0, s1);
    }
    __syncthreads();

    const int tx = tid & 31;
    const int wy = tid >> 5;   // warp -> code slice [64*wy, 64*wy+64)

    unsigned long long xq[4];
#pragma unroll
    for (int j = 0; j < 4; j++)
        xq[j] = *(const unsigned long long*)&sXsq[tx + 32 * j];

    const unsigned long long NEG2 = pk2(-2.0f, -2.0f);

    float best[8];
    int   bidx[8];
#pragma unroll
    for (int i = 0; i < 8; i++) { best[i] = 3.402823466e38f; bidx[i] = 0; }

    for (int blk = 0; blk < 8; blk++) {
        const int cb = wy * 64 + blk * 8;

        unsigned long long acc[32];
#pragma unroll
        for (int i = 0; i < 32; i++) acc[i] = 0ULL;

        const ulonglong2* ep = (const ulonglong2*)(sE + cb);          // +257 per d
        const unsigned long long* xp = (const unsigned long long*)sX + tx;  // +128 per d

        for (int k4 = 0; k4 < 8; k4++) {
#pragma unroll
            for (int ku = 0; ku < 4; ku++) {
                ulonglong2 E0 = ep[ku * 257 + 0];
                ulonglong2 E1 = ep[ku * 257 + 1];
                ulonglong2 E2 = ep[ku * 257 + 2];
                ulonglong2 E3 = ep[ku * 257 + 3];
                unsigned long long e8[8] = {E0.x, E0.y, E1.x, E1.y, E2.x, E2.y, E3.x, E3.y};
                unsigned long long xv[4];
                xv[0] = xp[ku * 128 + 0];
                xv[1] = xp[ku * 128 + 32];
                xv[2] = xp[ku * 128 + 64];
                xv[3] = xp[ku * 128 + 96];
#pragma unroll
                for (int c = 0; c < 8; c++)
#pragma unroll
                    for (int j = 0; j < 4; j++)
                        acc[c * 4 + j] = fma2(xv[j], e8[c], acc[c * 4 + j]);
            }
            ep += 4 * 257;
            xp += 4 * 128;
        }

        // finalize this 8-code block: dist = (e_sq + x_sq) - 2*dot
#pragma unroll
        for (int c = 0; c < 8; c++) {
            unsigned long long esq = *(const unsigned long long*)&sEsq[cb + c];
#pragma unroll
            for (int j = 0; j < 4; j++) {
                unsigned long long dd = fma2(acc[c * 4 + j], NEG2, add2(xq[j], esq));
                float d0, d1;
                upk2(dd, d0, d1);
                if (d0 < best[2 * j])     { best[2 * j] = d0;     bidx[2 * j] = cb + c; }
                if (d1 < best[2 * j + 1]) { best[2 * j + 1] = d1; bidx[2 * j + 1] = cb + c; }
            }
        }
    }

    // ---- cross-warp argmin: warps own ascending code slices ----
#pragma unroll
    for (int j = 0; j < 4; j++) {
        int p = tx + 32 * j;
        sBest[(2 * p) * 8 + wy]     = best[2 * j];
        sIdx [(2 * p) * 8 + wy]     = bidx[2 * j];
        sBest[(2 * p + 1) * 8 + wy] = best[2 * j + 1];
        sIdx [(2 * p + 1) * 8 + wy] = bidx[2 * j + 1];
    }
    __syncthreads();

    // ---- per-position epilogue (one thread per position) ----
    const int pid = tid;
    float bb = 3.402823466e38f;
    int   mi = 0;
#pragma unroll
    for (int w = 0; w < 8; w++) {
        float v = sBest[pid * 8 + w];
        if (v < bb) { bb = v; mi = sIdx[pid * 8 + w]; }
    }

    const int t = tile * 256 + pid;
    const int b = t >> 6, l = t & 63;

    out[OFF_IDX + (size_t)b * 256 + (size_t)n * 64 + l] = (float)mi;
    atomicAdd(&g_counts[n * M_CODES + mi], 1);

    float lloss = 0.0f;
    float* dwp = g_dw + ((size_t)n * M_CODES + mi) * D_DIM;
    float* zq  = out + OFF_ZQ + (size_t)b * 8192 + (size_t)n * 2048 + l;
#pragma unroll
    for (int d = 0; d < D_DIM; d++) {
        float2 xv2 = sX[d * 128 + (pid >> 1)];
        float xv = (pid & 1) ? xv2.y : xv2.x;
        float q  = sE[d * SE_STRIDE + mi].x;
        zq[d * 64] = __fsub_rn(__fadd_rn(q, xv), xv);
        float df = xv - q;
        lloss = fmaf(df, df, lloss);
        atomicAdd(dwp + d, xv);
    }

    // ---- CTA loss reduction -> one double atomic ----
#pragma unroll
    for (int o = 16; o > 0; o >>= 1) lloss += __shfl_down_sync(0xFFFFFFFFu, lloss, o);
    if (tx == 0) wsum[wy] = lloss;
    __syncthreads();
    if (tid == 0) {
        double s = 0.0;
#pragma unroll
        for (int w = 0; w < 8; w++) s += (double)wsum[w];
        atomicAdd(&g_loss, s);
    }
}

// ---------------- kernel 2: EMA / Laplace / embedding / perplexity / loss ----------------
__global__ void vq_fin(const float* __restrict__ ema_c,
                       const float* __restrict__ ema_w,
                       float* __restrict__ out) {
    const int n = blockIdx.x;
    const int m = threadIdx.x;   // 512 threads
    __shared__ float red[M_CODES];

    const float DECAY = 0.999f;
    const float OMD   = (float)(1.0 - 0.999);
    const float MEPS  = (float)(512.0 * 1e-5);

    float cnt  = (float)g_counts[n * M_CODES + m];
    float cnew = DECAY * ema_c[n * M_CODES + m] + OMD * cnt;

    red[m] = cnew;
    __syncthreads();
    for (int s = 256; s > 0; s >>= 1) {
        if (m < s) red[m] += red[m + s];
        __syncthreads();
    }
    float ntot = red[0];
    __syncthreads();

    float clap = (cnew + 1e-5f) / (ntot + MEPS) * ntot;
    out[OFF_CNT + (size_t)n * M_CODES + m] = clap;

#pragma unroll
    for (int d = 0; d < D_DIM; d++) {
        size_t idx = ((size_t)n * M_CODES + m) * D_DIM + d;
        float w = DECAY * ema_w[idx] + OMD * g_dw[idx];
        out[OFF_W + idx]   = w;
        out[OFF_EMB + idx] = w / clap;
    }

    float p    = cnt * (1.0f / 65536.0f);
    float term = p * logf(p + 1e-10f);
    red[m] = term;
    __syncthreads();
    for (int s = 256; s > 0; s >>= 1) {
        if (m < s) red[m] += red[m + s];
        __syncthreads();
    }
    if (m == 0) {
        atomicAdd(&out[OFF_PERP], expf(-red[0]));
        if (n == 0) out[OFF_LOSS] = (float)(0.25 * g_loss * (1.0 / 8388608.0));
    }
}

// ---------------- launch ----------------
extern "C" void kernel_launch(void* const* d_in, const int* in_sizes, int n_in,
                              void* d_out, int out_size) {
    const float* x     = (const float*)d_in[0];
    const float* emb   = (const float*)d_in[1];
    const float* ema_c = (const float*)d_in[2];
    const float* ema_w = (const float*)d_in[3];
    float* out = (float*)d_out;

    cudaFuncSetAttribute(vq_main, cudaFuncAttributeMaxDynamicSharedMemorySize, SMEM_BYTES);

    vq_zero<<<256, 256>>>(out);
    vq_main<<<dim3(T_POS / 256, N_CB), 256, SMEM_BYTES>>>(x, emb, out);
    vq_fin<<<N_CB, M_CODES>>>(ema_c, ema_w, out);
}